// round 3
// baseline (speedup 1.0000x reference)
#include <cuda_runtime.h>

#define BINS 64
#define BC 96                      // B*C = 32*3
#define PLANE 262144               // 512*512 elements per (b,c) plane
#define BLOCKS_PER_PLANE 16
#define CHUNK (PLANE / BLOCKS_PER_PLANE)   // 16384 floats per block per tensor
#define THREADS 256
#define NTOT 25165824              // 32*3*512*512

// Signed per-(plane,bin) count difference: +1 for input, -1 for target.
__device__ int g_diff[BC * BINS];

__global__ void zero_kernel() {
    int i = blockIdx.x * blockDim.x + threadIdx.x;
    if (i < BC * BINS) g_diff[i] = 0;
}

// bin = searchsorted(linspace(-1,1,64), v, side='right') - 1, clipped to [0,63],
// invalid (-1) if v < -1. Fast floor + exact edge correction.
__device__ __forceinline__ int bin_of(float v) {
    const float step = 2.0f / 63.0f;            // linspace spacing
    float t = (v + 1.0f) * 31.5f;               // (v+1)/step
    int j = (int)floorf(t);
    j = max(0, min(j, 63));
    // correct against actual f32 edge values (handles rounding at boundaries)
    float ej = fmaf((float)j, step, -1.0f);
    if (v < ej) {
        j -= 1;                                  // may become -1 (invalid, v < -1)
    } else if (j < 63) {
        float ej1 = fmaf((float)(j + 1), step, -1.0f);
        if (v >= ej1) j += 1;
    }
    return j;                                    // -1 => no bin
}

__global__ __launch_bounds__(THREADS)
void hist_kernel(const float4* __restrict__ inp, const float4* __restrict__ tgt) {
    // Lane-striped histogram: slot = bin*32 + lane. Within a warp, each lane
    // owns its own column -> zero intra-warp address OR bank conflicts.
    __shared__ int sh[BINS * 32];

    const int tid  = threadIdx.x;
    const int lane = tid & 31;

    #pragma unroll
    for (int i = tid; i < BINS * 32; i += THREADS) sh[i] = 0;
    __syncthreads();

    const int plane = blockIdx.x / BLOCKS_PER_PLANE;
    const int chunk = blockIdx.x % BLOCKS_PER_PLANE;
    const size_t base4 = (size_t)plane * (PLANE / 4) + (size_t)chunk * (CHUNK / 4);
    const float4* __restrict__ a = inp + base4;
    const float4* __restrict__ b = tgt + base4;
    const int n4 = CHUNK / 4;                    // 4096 float4 per tensor

    for (int i = tid; i < n4; i += THREADS) {
        float4 v = a[i];
        float4 u = b[i];
        int j;
        j = bin_of(v.x); if (j >= 0) atomicAdd(&sh[j * 32 + lane], 1);
        j = bin_of(v.y); if (j >= 0) atomicAdd(&sh[j * 32 + lane], 1);
        j = bin_of(v.z); if (j >= 0) atomicAdd(&sh[j * 32 + lane], 1);
        j = bin_of(v.w); if (j >= 0) atomicAdd(&sh[j * 32 + lane], 1);
        j = bin_of(u.x); if (j >= 0) atomicAdd(&sh[j * 32 + lane], -1);
        j = bin_of(u.y); if (j >= 0) atomicAdd(&sh[j * 32 + lane], -1);
        j = bin_of(u.z); if (j >= 0) atomicAdd(&sh[j * 32 + lane], -1);
        j = bin_of(u.w); if (j >= 0) atomicAdd(&sh[j * 32 + lane], -1);
    }
    __syncthreads();

    // Fold 32 lane-columns per bin, one global atomic per (block, bin).
    if (tid < BINS) {
        int s = 0;
        #pragma unroll
        for (int l = 0; l < 32; l++) s += sh[tid * 32 + l];
        if (s != 0) atomicAdd(&g_diff[plane * BINS + tid], s);
    }
}

__global__ void reduce_kernel(float* __restrict__ out) {
    __shared__ float ssum[THREADS / 32];
    float s = 0.0f;
    for (int i = threadIdx.x; i < BC * BINS; i += THREADS)
        s += fabsf((float)g_diff[i]);
    #pragma unroll
    for (int o = 16; o > 0; o >>= 1) s += __shfl_down_sync(0xFFFFFFFFu, s, o);
    if ((threadIdx.x & 31) == 0) ssum[threadIdx.x >> 5] = s;
    __syncthreads();
    if (threadIdx.x == 0) {
        float t = 0.0f;
        #pragma unroll
        for (int w = 0; w < THREADS / 32; w++) t += ssum[w];
        // loss = sum(|diff|)/N / (B*C*BINS)
        out[0] = t / ((float)PLANE * (float)(BC * BINS));
    }
}

extern "C" void kernel_launch(void* const* d_in, const int* in_sizes, int n_in,
                              void* d_out, int out_size) {
    const float* inp = (const float*)d_in[0];
    const float* tgt = (const float*)d_in[1];
    float* out = (float*)d_out;

    zero_kernel<<<(BC * BINS + 255) / 256, 256>>>();
    hist_kernel<<<BC * BLOCKS_PER_PLANE, THREADS>>>(
        (const float4*)inp, (const float4*)tgt);
    reduce_kernel<<<1, THREADS>>>(out);
}